// round 7
// baseline (speedup 1.0000x reference)
#include <cuda_runtime.h>

typedef unsigned long long ull;

// ---------------------------------------------------------------------------
// f32x2 helpers (packed dual-fp32 ops, sm_103a)
// ---------------------------------------------------------------------------
__device__ __forceinline__ ull pack2(float lo, float hi) {
    ull r; asm("mov.b64 %0, {%1, %2};" : "=l"(r) : "f"(lo), "f"(hi)); return r;
}
__device__ __forceinline__ void unpack2(ull v, float& lo, float& hi) {
    asm("mov.b64 {%0, %1}, %2;" : "=f"(lo), "=f"(hi) : "l"(v));
}
__device__ __forceinline__ ull fma2(ull a, ull b, ull c) {
    ull d; asm("fma.rn.f32x2 %0, %1, %2, %3;" : "=l"(d) : "l"(a), "l"(b), "l"(c)); return d;
}
__device__ __forceinline__ ull add2(ull a, ull b) {
    ull d; asm("add.rn.f32x2 %0, %1, %2;" : "=l"(d) : "l"(a), "l"(b)); return d;
}

#define CP_ASYNC16(dst_u32, src_ptr) \
    asm volatile("cp.async.cg.shared.global [%0], [%1], 16;" \
                 :: "r"(dst_u32), "l"(src_ptr) : "memory")
#define CP_COMMIT() asm volatile("cp.async.commit_group;" ::: "memory")
#define CP_WAIT1()  asm volatile("cp.async.wait_group 1;"  ::: "memory")

// Deferred epilogue: tanh + trig + per-wire combine + 4-lane reduce + store.
// Runs on E from the PREVIOUS iteration so its long-latency chain overlaps
// the current iteration's FMA block. Store predicated on `valid`.
__device__ __forceinline__ void epilogue(ull E, int baseRow, bool valid,
                                         float eb, float g1, float g2,
                                         float g3, float Cc, int lane,
                                         float* __restrict__ out) {
    float dlo, dhi;
    unpack2(E, dlo, dhi);
    const float dj = (lane & 1) ? dhi : dlo;
    const float t = dj + eb;
    const float e = __expf(2.0f * t);              // tanh = 1 - 2/(e^2t+1)
    const float th = 1.0f - __fdividef(2.0f, e + 1.0f);
    float sn, cs;
    __sincosf(th, &sn, &cs);
    const float cb  = __shfl_sync(0xffffffffu, cs, lane + 4);
    const float sb2 = __shfl_sync(0xffffffffu, sn, lane + 4);
    float r = fmaf(cs, fmaf(g2, sb2, g1 * cb), g3 * sn);
    r += __shfl_xor_sync(0xffffffffu, r, 1);
    r += __shfl_xor_sync(0xffffffffu, r, 2);
    if (valid && (lane & 7) == 0)
        out[baseRow + (lane >> 3)] = r + Cc;
}

// ---------------------------------------------------------------------------
// Single fused kernel, 4 rows / warp / iteration.
//  * x streamed via 3-stage cp.async SMEM ring (4KB/warp/stage, distance-2).
//  * enc_w in registers (f32x2).  Bit-fold reduce over lane bits
//    {8,16,4,2,1} -> lane L holds dot d_{L&7} of row L>>3, no redistribution.
//  * Epilogue software-pipelined one iteration behind (hides MUFU/SHFL chain
//    inside the next iteration's FMA block).
// ---------------------------------------------------------------------------
__global__ __launch_bounds__(256, 2)
void fused_kernel(const float4* __restrict__ x4,
                  const float4* __restrict__ w4,   // enc_w [8][256] as float4
                  const float* __restrict__ enc_b,
                  const float* __restrict__ rp,
                  const float* __restrict__ hw,
                  const float* __restrict__ hb,
                  float* __restrict__ out,
                  int B) {
    extern __shared__ float4 dynbuf[];   // 3 stages x 8 warps x 256 float4 = 96KB

    const int lane = threadIdx.x & 31;
    const int wIn  = threadIdx.x >> 5;
    const int warpId = (blockIdx.x * blockDim.x + threadIdx.x) >> 5;
    const int W = (gridDim.x * blockDim.x) >> 5;

    const unsigned sbase =
        (unsigned)__cvta_generic_to_shared(dynbuf + (size_t)wIn * 256 + lane);

    const int nQuads = B >> 2;   // 4 rows (1KB each) per quad

    // ---- prologue: issue quads warpId (stage0), warpId+W (stage1) ----
#pragma unroll
    for (int i = 0; i < 2; ++i) {
        const int q = warpId + i * W;
        if (q < nQuads) {
            const float4* g = x4 + (size_t)q * 256 + lane;
            const unsigned d = sbase + (unsigned)i * 32768u;
#pragma unroll
            for (int j = 0; j < 8; ++j) CP_ASYNC16(d + j * 512u, g + j * 32);
        }
        CP_COMMIT();
    }

    // ---- enc_w into registers (latency hidden by constant folding below) --
    ull wreg[4][2][4];
#pragma unroll
    for (int p = 0; p < 4; ++p)
#pragma unroll
        for (int c = 0; c < 2; ++c) {
            float4 a = w4[(2 * p) * 64 + c * 32 + lane];
            float4 b = w4[(2 * p + 1) * 64 + c * 32 + lane];
            wreg[p][c][0] = pack2(a.x, b.x);
            wreg[p][c][1] = pack2(a.y, b.y);
            wreg[p][c][2] = pack2(a.z, b.z);
            wreg[p][c][3] = pack2(a.w, b.w);
        }

    // ---- fold fixed circuit: wire w = lane&3, fp32 -----------------------
    float g1, g2, g3, Cc;
    {
        const int w = lane & 3;
        float ur00 = 1.f, ui00 = 0.f, ur01 = 0.f, ui01 = 0.f;
        float ur10 = 0.f, ui10 = 0.f, ur11 = 1.f, ui11 = 0.f;
        for (int k = w; k < 30; k += 4) {
            float s, c;
            __sincosf(rp[k] * 0.5f, &s, &c);
            const int g = k % 3;
            const float gi01 = (g == 0) ? -s : 0.f;  // RX
            const float gi10 = (g == 0) ? -s : 0.f;
            const float gr01 = (g == 1) ? -s : 0.f;  // RY
            const float gr10 = (g == 1) ?  s : 0.f;
            const float gi00 = (g == 2) ? -s : 0.f;  // RZ
            const float gi11 = (g == 2) ?  s : 0.f;
            const float nr00 = c*ur00 - gi00*ui00 + gr01*ur10 - gi01*ui10;
            const float ni00 = c*ui00 + gi00*ur00 + gr01*ui10 + gi01*ur10;
            const float nr01 = c*ur01 - gi00*ui01 + gr01*ur11 - gi01*ui11;
            const float ni01 = c*ui01 + gi00*ur01 + gr01*ui11 + gi01*ur11;
            const float nr10 = gr10*ur00 - gi10*ui00 + c*ur10 - gi11*ui10;
            const float ni10 = gr10*ui00 + gi10*ur00 + c*ui10 + gi11*ur10;
            const float nr11 = gr10*ur01 - gi10*ui01 + c*ur11 - gi11*ui11;
            const float ni11 = gr10*ui01 + gi10*ur01 + c*ui11 + gi11*ur11;
            ur00 = nr00; ui00 = ni00; ur01 = nr01; ui01 = ni01;
            ur10 = nr10; ui10 = ni10; ur11 = nr11; ui11 = ni11;
        }
        const float m00  = ur00*ur00 + ui00*ui00 - (ur10*ur10 + ui10*ui10);
        const float m11  = ur01*ur01 + ui01*ui01 - (ur11*ur11 + ui11*ui11);
        const float m01r = (ur00*ur01 + ui00*ui01) - (ur10*ur11 + ui10*ui11);
        const float m01i = (ur00*ui01 - ui00*ur01) - (ur10*ui11 - ui10*ur11);
        const float h = hw[w];
        g1 = h * 0.5f * (m00 - m11);
        g2 = h * m01r;
        g3 = h * m01i;
        float c0w = h * 0.5f * (m00 + m11);
        c0w += __shfl_xor_sync(0xffffffffu, c0w, 1);
        c0w += __shfl_xor_sync(0xffffffffu, c0w, 2);
        Cc = hb[0] + c0w;
    }

    const float eb = enc_b[lane & 7];

    // deferred-epilogue carry state
    ull Eprev = 0;
    int prevBase = -1;

    int sp = 0;
    for (int quad = warpId; quad < nQuads; quad += W) {
        CP_WAIT1();   // current stage landed

        // prefetch quad+2W into stage (sp+2)%3 == stage read LAST iteration
        // (WAR-safe; issuing before our LDS reads gives the copies a head start)
        {
            const int pf = quad + 2 * W;
            const int fs = (sp + 2 >= 3) ? sp - 1 : sp + 2;
            if (pf < nQuads) {
                const float4* g = x4 + (size_t)pf * 256 + lane;
                const unsigned d = sbase + (unsigned)fs * 32768u;
#pragma unroll
                for (int j = 0; j < 8; ++j) CP_ASYNC16(d + j * 512u, g + j * 32);
            }
            CP_COMMIT();
        }

        const float4* sptr = dynbuf + ((sp * 8 + wIn) * 256) + lane;

        // ---- rows 0,1: accumulate then fold row-parity (lane bit 3) ----
        const float4 x0a = sptr[0],   x0b = sptr[32];
        const float4 x1a = sptr[64],  x1b = sptr[96];
        ull B01[4];
        {
            ull a0[4] = {0,0,0,0}, a1[4] = {0,0,0,0};
            const float xs0[8] = {x0a.x, x0a.y, x0a.z, x0a.w, x0b.x, x0b.y, x0b.z, x0b.w};
            const float xs1[8] = {x1a.x, x1a.y, x1a.z, x1a.w, x1b.x, x1b.y, x1b.z, x1b.w};
#pragma unroll
            for (int q = 0; q < 8; ++q) {
                const int c = q >> 2, j = q & 3;
                const ull xx0 = pack2(xs0[q], xs0[q]);
                const ull xx1 = pack2(xs1[q], xs1[q]);
#pragma unroll
                for (int p = 0; p < 4; ++p) {
                    a0[p] = fma2(xx0, wreg[p][c][j], a0[p]);
                    a1[p] = fma2(xx1, wreg[p][c][j], a1[p]);
                }
            }
#pragma unroll
            for (int p = 0; p < 4; ++p) {
                const ull mine  = (lane & 8) ? a1[p] : a0[p];
                const ull other = (lane & 8) ? a0[p] : a1[p];
                B01[p] = add2(mine, __shfl_xor_sync(0xffffffffu, other, 8));
            }
        }

        // ---- deferred epilogue for the PREVIOUS quad (independent chain;
        //      ptxas interleaves its MUFU/SHFL stalls with the FMAs around) --
        epilogue(Eprev, prevBase, prevBase >= 0, eb, g1, g2, g3, Cc, lane, out);

        // ---- rows 2,3 ----
        const float4 x2a = sptr[128], x2b = sptr[160];
        const float4 x3a = sptr[192], x3b = sptr[224];
        ull B23[4];
        {
            ull a2[4] = {0,0,0,0}, a3[4] = {0,0,0,0};
            const float xs2[8] = {x2a.x, x2a.y, x2a.z, x2a.w, x2b.x, x2b.y, x2b.z, x2b.w};
            const float xs3[8] = {x3a.x, x3a.y, x3a.z, x3a.w, x3b.x, x3b.y, x3b.z, x3b.w};
#pragma unroll
            for (int q = 0; q < 8; ++q) {
                const int c = q >> 2, j = q & 3;
                const ull xx2 = pack2(xs2[q], xs2[q]);
                const ull xx3 = pack2(xs3[q], xs3[q]);
#pragma unroll
                for (int p = 0; p < 4; ++p) {
                    a2[p] = fma2(xx2, wreg[p][c][j], a2[p]);
                    a3[p] = fma2(xx3, wreg[p][c][j], a3[p]);
                }
            }
#pragma unroll
            for (int p = 0; p < 4; ++p) {
                const ull mine  = (lane & 8) ? a3[p] : a2[p];
                const ull other = (lane & 8) ? a2[p] : a3[p];
                B23[p] = add2(mine, __shfl_xor_sync(0xffffffffu, other, 8));
            }
        }

        // ---- remaining fold levels: bits 16, 4, 2, 1 ----
        ull C[4];
#pragma unroll
        for (int p = 0; p < 4; ++p) {
            const ull mine  = (lane & 16) ? B23[p] : B01[p];
            const ull other = (lane & 16) ? B01[p] : B23[p];
            C[p] = add2(mine, __shfl_xor_sync(0xffffffffu, other, 16));
        }
        ull D0 = add2((lane & 4) ? C[2] : C[0],
                      __shfl_xor_sync(0xffffffffu, (lane & 4) ? C[0] : C[2], 4));
        ull D1 = add2((lane & 4) ? C[3] : C[1],
                      __shfl_xor_sync(0xffffffffu, (lane & 4) ? C[1] : C[3], 4));
        ull E = add2((lane & 2) ? D1 : D0,
                     __shfl_xor_sync(0xffffffffu, (lane & 2) ? D0 : D1, 2));
        E = add2(E, __shfl_xor_sync(0xffffffffu, E, 1));
        // lane L holds dot d_{L&7} of row L>>3.

        Eprev = E;
        prevBase = 4 * quad;

        sp = (sp + 1 >= 3) ? 0 : sp + 1;
    }

    // drain the deferred epilogue for the final quad
    epilogue(Eprev, prevBase, prevBase >= 0, eb, g1, g2, g3, Cc, lane, out);
}

extern "C" void kernel_launch(void* const* d_in, const int* in_sizes, int n_in,
                              void* d_out, int out_size) {
    const float* x     = (const float*)d_in[0];
    const float* enc_w = (const float*)d_in[1];
    const float* enc_b = (const float*)d_in[2];
    const float* rp    = (const float*)d_in[3];
    const float* hw    = (const float*)d_in[4];
    const float* hb    = (const float*)d_in[5];
    float* out = (float*)d_out;

    const int B = in_sizes[0] / 256;  // F = 256

    const int SMEM = 3 * 8 * 256 * sizeof(float4);  // 96 KB
    cudaFuncSetAttribute(fused_kernel,
                         cudaFuncAttributeMaxDynamicSharedMemorySize, SMEM);
    fused_kernel<<<296, 256, SMEM>>>((const float4*)x, (const float4*)enc_w,
                                     enc_b, rp, hw, hb, out, B);
}